// round 16
// baseline (speedup 1.0000x reference)
#include <cuda_runtime.h>
#include <cuda_fp16.h>
#include <cstdint>

// KPConv fully tensorized, pipelined, small-CTA (R9 baseline) + branch-free
// phase-1 (padded kp table, sqrtf kept) + phase-3 B fragments via LDG.128.
// inputs: q_pts[N,3], s_pts(unused), neighbors[N,32,3], neighb_inds(unused),
//         x[N,32,64], kernel_points[15,3], weights[15,64,64] -> out[N,64] f32

#define KPTS 15
#define NNB  32
#define CIN  64
#define COUT 64
#define PBLK 16
#define QB   2
#define NQB  8
#define THREADS 256
#define NKS  60                  // 960 / 16
#define ROWB 1920                // wt row stride bytes
#define WT_BYTES (PBLK * ROWB)   // 30720
#define XSH_OFF  WT_BYTES
#define XBUF     8192            // 2 pts * 4096
#define W16_OFF  (XSH_OFF + 2 * XBUF)        // 47104
#define WBUF     2560                        // 2 pts * 1280
#define SMEM_TOTAL (W16_OFF + 2 * WBUF + 1024)

typedef unsigned long long ull;

// B fragments, packed for LDG.128: [ng(4)][ks(60)][lane(32)] -> uint4
//   {nt=2ng: b0,b1,  nt=2ng+1: b0,b1}
__device__ uint4 g_Bfrag4[4 * NKS * 32];

static __device__ __forceinline__ uint32_t smem_u32(const void* p) {
    uint32_t a;
    asm("{ .reg .u64 t; cvta.to.shared.u64 t, %1; cvt.u32.u64 %0, t; }" : "=r"(a) : "l"(p));
    return a;
}
static __device__ __forceinline__ void ldm_x4(uint32_t& a0, uint32_t& a1,
                                              uint32_t& a2, uint32_t& a3, uint32_t addr) {
    asm volatile("ldmatrix.sync.aligned.m8n8.x4.shared.b16 {%0,%1,%2,%3}, [%4];"
                 : "=r"(a0), "=r"(a1), "=r"(a2), "=r"(a3) : "r"(addr));
}
static __device__ __forceinline__ void ldm_x4t(uint32_t& a0, uint32_t& a1,
                                               uint32_t& a2, uint32_t& a3, uint32_t addr) {
    asm volatile("ldmatrix.sync.aligned.m8n8.x4.trans.shared.b16 {%0,%1,%2,%3}, [%4];"
                 : "=r"(a0), "=r"(a1), "=r"(a2), "=r"(a3) : "r"(addr));
}
static __device__ __forceinline__ void mma16816(float* c, uint32_t a0, uint32_t a1,
                                                uint32_t a2, uint32_t a3,
                                                uint32_t b0, uint32_t b1) {
    asm volatile("mma.sync.aligned.m16n8k16.row.col.f32.f16.f16.f32 "
                 "{%0,%1,%2,%3}, {%4,%5,%6,%7}, {%8,%9}, {%0,%1,%2,%3};"
                 : "+f"(c[0]), "+f"(c[1]), "+f"(c[2]), "+f"(c[3])
                 : "r"(a0), "r"(a1), "r"(a2), "r"(a3), "r"(b0), "r"(b1));
}
static __device__ __forceinline__ uint32_t h2u(float lo, float hi) {
    __half2 h = __floats2half2_rn(lo, hi);
    return *(const uint32_t*)&h;
}

__global__ void pack_bfrag(const float* __restrict__ W) {
    int i = blockIdx.x * blockDim.x + threadIdx.x;
    if (i >= 4 * NKS * 32) return;
    int lane = i & 31;
    int ks   = (i >> 5) % NKS;
    int ng   = i / (NKS * 32);
    int n0 = ng * 16 + (lane >> 2);
    int n1 = n0 + 8;
    int j0 = ks * 16 + (lane & 3) * 2;
    uint4 u;
    u.x = h2u(W[(j0 + 0) * COUT + n0], W[(j0 + 1) * COUT + n0]);
    u.y = h2u(W[(j0 + 8) * COUT + n0], W[(j0 + 9) * COUT + n0]);
    u.z = h2u(W[(j0 + 0) * COUT + n1], W[(j0 + 1) * COUT + n1]);
    u.w = h2u(W[(j0 + 8) * COUT + n1], W[(j0 + 9) * COUT + n1]);
    g_Bfrag4[i] = u;
}

__global__ __launch_bounds__(THREADS, 4)
void kpconv_kernel(const float* __restrict__ q_pts,
                   const float* __restrict__ neighbors,
                   const float* __restrict__ x,
                   const float* __restrict__ kernel_points,
                   float* __restrict__ out,
                   int N)
{
    extern __shared__ char smem_raw[];
    char* smem = (char*)(((uintptr_t)smem_raw + 1023) & ~(uintptr_t)1023);
    char* wt_sh = smem;                      // fp16 A tile for phase 3 (16 rows)
    char* x_sh  = smem + XSH_OFF;            // fp16 x tiles, 2 bufs x 2 pts
    char* w16   = smem + W16_OFF;            // fp16 w tiles, 2 bufs x 2 pts
    __shared__ float kp_sh[16 * 3];          // pad row k=15 at 1e4 -> w = 0
    const uint32_t sb_u32  = smem_u32(smem);
    const uint32_t wt_u32  = sb_u32;
    const uint32_t xsh_u32 = sb_u32 + XSH_OFF;
    const uint32_t w16_u32 = sb_u32 + W16_OFF;

    const int tid  = threadIdx.x;
    const int wid  = tid >> 5;
    const int lane = tid & 31;
    const int base = blockIdx.x * PBLK;

    if (tid < 16 * 3) kp_sh[tid] = (tid < KPTS * 3) ? kernel_points[tid] : 1.0e4f;
    __syncthreads();

    const float inv_ext = 1.0f / 0.06f;

    // staging geometry: warp -> point (wid>>2), row group (wid&3)
    const int sp  = wid >> 2;
    const int rg  = wid & 3;
    // phase1 geometry: item i = tid>>2 (p1, m1), k-quarter kq = tid&3
    const int i1  = tid >> 2;
    const int p1  = i1 >> 5;
    const int m1  = i1 & 31;
    const int kq  = tid & 3;

    float4 xf[4];
    float rx, ry, rz;

#define LDG_X(qb)                                                            \
    {                                                                        \
        int np = base + (qb) * QB + sp; if (np >= N) np = N - 1;             \
        const float4* xr = (const float4*)(x + (long long)np * NNB * CIN);   \
        _Pragma("unroll")                                                    \
        for (int it = 0; it < 4; it++) {                                     \
            int m = rg * 8 + it * 2 + (lane >> 4);                           \
            xf[it] = __ldg(xr + m * 16 + (lane & 15));                       \
        }                                                                    \
    }

#define LDG_NBR(qb)                                                          \
    {                                                                        \
        int np = base + (qb) * QB + p1; if (np >= N) np = N - 1;             \
        float qx = q_pts[np * 3 + 0];                                        \
        float qy = q_pts[np * 3 + 1];                                        \
        float qz = q_pts[np * 3 + 2];                                        \
        int nb = (np * NNB + m1) * 3;                                        \
        rx = neighbors[nb + 0] - qx;                                         \
        ry = neighbors[nb + 1] - qy;                                         \
        rz = neighbors[nb + 2] - qz;                                         \
    }

#define PHASE1_ST(buf)                                                       \
    {                                                                        \
        char* wrow = w16 + (buf) * WBUF + p1 * 1280 + m1 * 2;                \
        _Pragma("unroll")                                                    \
        for (int kk = 0; kk < 4; kk++) {                                     \
            int k = kq * 4 + kk;                                             \
            float dx = rx - kp_sh[k * 3 + 0];                                \
            float dy = ry - kp_sh[k * 3 + 1];                                \
            float dz = rz - kp_sh[k * 3 + 2];                                \
            float sq = dx * dx + dy * dy + dz * dz;                          \
            float w = fmaxf(1.0f - sqrtf(sq) * inv_ext, 0.0f);               \
            *(__half*)(wrow + k * 80) = __float2half_rn(w);                  \
        }                                                                    \
    }

#define STS_X(buf)                                                           \
    {                                                                        \
        char* xt = x_sh + (buf) * XBUF + sp * 4096;                          \
        _Pragma("unroll")                                                    \
        for (int it = 0; it < 4; it++) {                                     \
            int m  = rg * 8 + it * 2 + (lane >> 4);                          \
            int c4 = (lane & 15) * 4;                                        \
            uint2 st;                                                        \
            st.x = h2u(xf[it].x, xf[it].y);                                  \
            st.y = h2u(xf[it].z, xf[it].w);                                  \
            int chunk = (c4 >> 3) ^ (m & 7);                                 \
            *(uint2*)(xt + m * 128 + chunk * 16 + (c4 & 7) * 2) = st;        \
        }                                                                    \
    }

    // ---------- prologue ----------
    LDG_X(0)
    LDG_NBR(0)
    PHASE1_ST(0)
    STS_X(0)
    __syncthreads();

    // ---------- pipelined main loop ----------
    #pragma unroll 1
    for (int q = 0; q < NQB; q++) {
        if (q < NQB - 1) {
            LDG_X(q + 1)
            LDG_NBR(q + 1)
        }

        // ---- phase2 MMA for qb=q: wt[16][64] = w[16][32] @ x[32][64] ----
        {
            const int buf = q & 1;
            const int p  = wid >> 2;             // 0..1
            const int qn = wid & 3;              // nt pair
            uint32_t wp = w16_u32 + buf * WBUF + p * 1280;
            uint32_t xp = xsh_u32 + buf * XBUF + p * 4096;
            int g = lane >> 3;

            float d0[4] = {0.f, 0.f, 0.f, 0.f};
            float d1[4] = {0.f, 0.f, 0.f, 0.f};
            #pragma unroll
            for (int s = 0; s < 2; s++) {
                uint32_t a0, a1, a2, a3;
                ldm_x4(a0, a1, a2, a3,
                       wp + ((g & 1) * 8 + (lane & 7)) * 80 + s * 32 + (g >> 1) * 16);
                int row = s * 16 + (g & 1) * 8 + (lane & 7);
                int nt  = qn * 2 + (g >> 1);
                uint32_t b0, b1, b2, b3;
                ldm_x4t(b0, b1, b2, b3,
                        xp + row * 128 + ((nt ^ (row & 7)) << 4));
                mma16816(d0, a0, a1, a2, a3, b0, b1);
                mma16816(d1, a0, a1, a2, a3, b2, b3);
            }

            // store D -> WT tile (phase-3 A layout)
            int lr = q * QB + p;
            char* row_ = wt_sh + lr * ROWB;
            int sw = lr & 7;
            #pragma unroll
            for (int i = 0; i < 2; i++) {
                const float* dd = i ? d1 : d0;
                #pragma unroll
                for (int rh = 0; rh < 2; rh++) {
                    int kpt = (lane >> 2) + rh * 8;
                    if (kpt < KPTS) {
                        int c = (qn * 2 + i) * 8 + (lane & 3) * 2;
                        __half2 h = __floats2half2_rn(dd[rh * 2], dd[rh * 2 + 1]);
                        int chunk = (kpt * 8 + (c >> 3)) ^ sw;
                        *(__half2*)(row_ + chunk * 16 + (c & 7) * 2) = h;
                    }
                }
            }
        }

        if (q < NQB - 1) {
            PHASE1_ST((q + 1) & 1)
            STS_X((q + 1) & 1)
        }
        __syncthreads();
    }

    // ---------- Phase 3: HMMA GEMM out[16][64] = wt @ W ----------
    {
        const int kh = wid >> 2;                 // K-half
        const int ng = wid & 3;                  // n-group (2 n-tiles)
        const int rowA = lane & 15;
        const uint32_t a_row = wt_u32 + rowA * ROWB;
        const int swA = rowA & 7;
        const int khalf = lane >> 4;

        float c0[4] = {0.f, 0.f, 0.f, 0.f};
        float c1[4] = {0.f, 0.f, 0.f, 0.f};
        const uint4* Bf = g_Bfrag4 + (ng * NKS + kh * (NKS / 2)) * 32 + lane;

        #pragma unroll 5
        for (int s = 0; s < NKS / 2; s++) {
            int ks = kh * (NKS / 2) + s;
            uint32_t addr = a_row + ((((ks << 1) + khalf) ^ swA) << 4);
            uint32_t a0, a1, a2, a3;
            ldm_x4(a0, a1, a2, a3, addr);
            uint4 b = __ldg(Bf + s * 32);
            mma16816(c0, a0, a1, a2, a3, b.x, b.y);
            mma16816(c1, a0, a1, a2, a3, b.z, b.w);
        }

        // reduce across K-halves via smem (alias over x_sh)
        float4* red4 = (float4*)x_sh;            // 4KB <= 16KB
        __syncthreads();
        if (kh == 1) {
            red4[(ng * 2 + 0) * 32 + lane] = make_float4(c0[0], c0[1], c0[2], c0[3]);
            red4[(ng * 2 + 1) * 32 + lane] = make_float4(c1[0], c1[1], c1[2], c1[3]);
        }
        __syncthreads();
        if (kh == 0) {
            float4 r0 = red4[(ng * 2 + 0) * 32 + lane];
            float4 r1 = red4[(ng * 2 + 1) * 32 + lane];
            c0[0] += r0.x; c0[1] += r0.y; c0[2] += r0.z; c0[3] += r0.w;
            c1[0] += r1.x; c1[1] += r1.y; c1[2] += r1.z; c1[3] += r1.w;
            int ro0 = base + (lane >> 2);
            int ro1 = ro0 + 8;
            int col0 = (ng * 2 + 0) * 8 + (lane & 3) * 2;
            int col1 = (ng * 2 + 1) * 8 + (lane & 3) * 2;
            if (ro0 < N) {
                *(float2*)&out[(long long)ro0 * COUT + col0] = make_float2(c0[0], c0[1]);
                *(float2*)&out[(long long)ro0 * COUT + col1] = make_float2(c1[0], c1[1]);
            }
            if (ro1 < N) {
                *(float2*)&out[(long long)ro1 * COUT + col0] = make_float2(c0[2], c0[3]);
                *(float2*)&out[(long long)ro1 * COUT + col1] = make_float2(c1[2], c1[3]);
            }
        }
    }
}

extern "C" void kernel_launch(void* const* d_in, const int* in_sizes, int n_in,
                              void* d_out, int out_size) {
    const float* q_pts     = (const float*)d_in[0];
    const float* neighbors = (const float*)d_in[2];
    const float* x         = (const float*)d_in[4];
    const float* kp        = (const float*)d_in[5];
    const float* W         = (const float*)d_in[6];
    float* out = (float*)d_out;

    int N = in_sizes[0] / 3;

    cudaFuncSetAttribute(kpconv_kernel,
                         cudaFuncAttributeMaxDynamicSharedMemorySize, SMEM_TOTAL);

    pack_bfrag<<<(4 * NKS * 32 + 255) / 256, 256>>>(W);
    int grid = (N + PBLK - 1) / PBLK;
    kpconv_kernel<<<grid, THREADS, SMEM_TOTAL>>>(q_pts, neighbors, x, kp, out, N);
}

// round 17
// speedup vs baseline: 1.4091x; 1.4091x over previous
#include <cuda_runtime.h>
#include <cuda_fp16.h>
#include <cstdint>

// KPConv fully tensorized, pipelined, small-CTA (R9 baseline) + branch-free
// phase-1 (padded kp table, sqrtf kept) + phase-3 B fragments via LDG.128.
// (R16 content resubmitted verbatim: cross-round metric analysis shows the
//  R15/R16 wall-clock regressions were DVFS downclock, not kernel content —
//  clock-normalized this is the fastest variant, ~117 norm-us vs R9's 132.)
// inputs: q_pts[N,3], s_pts(unused), neighbors[N,32,3], neighb_inds(unused),
//         x[N,32,64], kernel_points[15,3], weights[15,64,64] -> out[N,64] f32

#define KPTS 15
#define NNB  32
#define CIN  64
#define COUT 64
#define PBLK 16
#define QB   2
#define NQB  8
#define THREADS 256
#define NKS  60                  // 960 / 16
#define ROWB 1920                // wt row stride bytes
#define WT_BYTES (PBLK * ROWB)   // 30720
#define XSH_OFF  WT_BYTES
#define XBUF     8192            // 2 pts * 4096
#define W16_OFF  (XSH_OFF + 2 * XBUF)        // 47104
#define WBUF     2560                        // 2 pts * 1280
#define SMEM_TOTAL (W16_OFF + 2 * WBUF + 1024)

typedef unsigned long long ull;

// B fragments, packed for LDG.128: [ng(4)][ks(60)][lane(32)] -> uint4
//   {nt=2ng: b0,b1,  nt=2ng+1: b0,b1}
__device__ uint4 g_Bfrag4[4 * NKS * 32];

static __device__ __forceinline__ uint32_t smem_u32(const void* p) {
    uint32_t a;
    asm("{ .reg .u64 t; cvta.to.shared.u64 t, %1; cvt.u32.u64 %0, t; }" : "=r"(a) : "l"(p));
    return a;
}
static __device__ __forceinline__ void ldm_x4(uint32_t& a0, uint32_t& a1,
                                              uint32_t& a2, uint32_t& a3, uint32_t addr) {
    asm volatile("ldmatrix.sync.aligned.m8n8.x4.shared.b16 {%0,%1,%2,%3}, [%4];"
                 : "=r"(a0), "=r"(a1), "=r"(a2), "=r"(a3) : "r"(addr));
}
static __device__ __forceinline__ void ldm_x4t(uint32_t& a0, uint32_t& a1,
                                               uint32_t& a2, uint32_t& a3, uint32_t addr) {
    asm volatile("ldmatrix.sync.aligned.m8n8.x4.trans.shared.b16 {%0,%1,%2,%3}, [%4];"
                 : "=r"(a0), "=r"(a1), "=r"(a2), "=r"(a3) : "r"(addr));
}
static __device__ __forceinline__ void mma16816(float* c, uint32_t a0, uint32_t a1,
                                                uint32_t a2, uint32_t a3,
                                                uint32_t b0, uint32_t b1) {
    asm volatile("mma.sync.aligned.m16n8k16.row.col.f32.f16.f16.f32 "
                 "{%0,%1,%2,%3}, {%4,%5,%6,%7}, {%8,%9}, {%0,%1,%2,%3};"
                 : "+f"(c[0]), "+f"(c[1]), "+f"(c[2]), "+f"(c[3])
                 : "r"(a0), "r"(a1), "r"(a2), "r"(a3), "r"(b0), "r"(b1));
}
static __device__ __forceinline__ uint32_t h2u(float lo, float hi) {
    __half2 h = __floats2half2_rn(lo, hi);
    return *(const uint32_t*)&h;
}

__global__ void pack_bfrag(const float* __restrict__ W) {
    int i = blockIdx.x * blockDim.x + threadIdx.x;
    if (i >= 4 * NKS * 32) return;
    int lane = i & 31;
    int ks   = (i >> 5) % NKS;
    int ng   = i / (NKS * 32);
    int n0 = ng * 16 + (lane >> 2);
    int n1 = n0 + 8;
    int j0 = ks * 16 + (lane & 3) * 2;
    uint4 u;
    u.x = h2u(W[(j0 + 0) * COUT + n0], W[(j0 + 1) * COUT + n0]);
    u.y = h2u(W[(j0 + 8) * COUT + n0], W[(j0 + 9) * COUT + n0]);
    u.z = h2u(W[(j0 + 0) * COUT + n1], W[(j0 + 1) * COUT + n1]);
    u.w = h2u(W[(j0 + 8) * COUT + n1], W[(j0 + 9) * COUT + n1]);
    g_Bfrag4[i] = u;
}

__global__ __launch_bounds__(THREADS, 4)
void kpconv_kernel(const float* __restrict__ q_pts,
                   const float* __restrict__ neighbors,
                   const float* __restrict__ x,
                   const float* __restrict__ kernel_points,
                   float* __restrict__ out,
                   int N)
{
    extern __shared__ char smem_raw[];
    char* smem = (char*)(((uintptr_t)smem_raw + 1023) & ~(uintptr_t)1023);
    char* wt_sh = smem;                      // fp16 A tile for phase 3 (16 rows)
    char* x_sh  = smem + XSH_OFF;            // fp16 x tiles, 2 bufs x 2 pts
    char* w16   = smem + W16_OFF;            // fp16 w tiles, 2 bufs x 2 pts
    __shared__ float kp_sh[16 * 3];          // pad row k=15 at 1e4 -> w = 0
    const uint32_t sb_u32  = smem_u32(smem);
    const uint32_t wt_u32  = sb_u32;
    const uint32_t xsh_u32 = sb_u32 + XSH_OFF;
    const uint32_t w16_u32 = sb_u32 + W16_OFF;

    const int tid  = threadIdx.x;
    const int wid  = tid >> 5;
    const int lane = tid & 31;
    const int base = blockIdx.x * PBLK;

    if (tid < 16 * 3) kp_sh[tid] = (tid < KPTS * 3) ? kernel_points[tid] : 1.0e4f;
    __syncthreads();

    const float inv_ext = 1.0f / 0.06f;

    // staging geometry: warp -> point (wid>>2), row group (wid&3)
    const int sp  = wid >> 2;
    const int rg  = wid & 3;
    // phase1 geometry: item i = tid>>2 (p1, m1), k-quarter kq = tid&3
    const int i1  = tid >> 2;
    const int p1  = i1 >> 5;
    const int m1  = i1 & 31;
    const int kq  = tid & 3;

    float4 xf[4];
    float rx, ry, rz;

#define LDG_X(qb)                                                            \
    {                                                                        \
        int np = base + (qb) * QB + sp; if (np >= N) np = N - 1;             \
        const float4* xr = (const float4*)(x + (long long)np * NNB * CIN);   \
        _Pragma("unroll")                                                    \
        for (int it = 0; it < 4; it++) {                                     \
            int m = rg * 8 + it * 2 + (lane >> 4);                           \
            xf[it] = __ldg(xr + m * 16 + (lane & 15));                       \
        }                                                                    \
    }

#define LDG_NBR(qb)                                                          \
    {                                                                        \
        int np = base + (qb) * QB + p1; if (np >= N) np = N - 1;             \
        float qx = q_pts[np * 3 + 0];                                        \
        float qy = q_pts[np * 3 + 1];                                        \
        float qz = q_pts[np * 3 + 2];                                        \
        int nb = (np * NNB + m1) * 3;                                        \
        rx = neighbors[nb + 0] - qx;                                         \
        ry = neighbors[nb + 1] - qy;                                         \
        rz = neighbors[nb + 2] - qz;                                         \
    }

#define PHASE1_ST(buf)                                                       \
    {                                                                        \
        char* wrow = w16 + (buf) * WBUF + p1 * 1280 + m1 * 2;                \
        _Pragma("unroll")                                                    \
        for (int kk = 0; kk < 4; kk++) {                                     \
            int k = kq * 4 + kk;                                             \
            float dx = rx - kp_sh[k * 3 + 0];                                \
            float dy = ry - kp_sh[k * 3 + 1];                                \
            float dz = rz - kp_sh[k * 3 + 2];                                \
            float sq = dx * dx + dy * dy + dz * dz;                          \
            float w = fmaxf(1.0f - sqrtf(sq) * inv_ext, 0.0f);               \
            *(__half*)(wrow + k * 80) = __float2half_rn(w);                  \
        }                                                                    \
    }

#define STS_X(buf)                                                           \
    {                                                                        \
        char* xt = x_sh + (buf) * XBUF + sp * 4096;                          \
        _Pragma("unroll")                                                    \
        for (int it = 0; it < 4; it++) {                                     \
            int m  = rg * 8 + it * 2 + (lane >> 4);                          \
            int c4 = (lane & 15) * 4;                                        \
            uint2 st;                                                        \
            st.x = h2u(xf[it].x, xf[it].y);                                  \
            st.y = h2u(xf[it].z, xf[it].w);                                  \
            int chunk = (c4 >> 3) ^ (m & 7);                                 \
            *(uint2*)(xt + m * 128 + chunk * 16 + (c4 & 7) * 2) = st;        \
        }                                                                    \
    }

    // ---------- prologue ----------
    LDG_X(0)
    LDG_NBR(0)
    PHASE1_ST(0)
    STS_X(0)
    __syncthreads();

    // ---------- pipelined main loop ----------
    #pragma unroll 1
    for (int q = 0; q < NQB; q++) {
        if (q < NQB - 1) {
            LDG_X(q + 1)
            LDG_NBR(q + 1)
        }

        // ---- phase2 MMA for qb=q: wt[16][64] = w[16][32] @ x[32][64] ----
        {
            const int buf = q & 1;
            const int p  = wid >> 2;             // 0..1
            const int qn = wid & 3;              // nt pair
            uint32_t wp = w16_u32 + buf * WBUF + p * 1280;
            uint32_t xp = xsh_u32 + buf * XBUF + p * 4096;
            int g = lane >> 3;

            float d0[4] = {0.f, 0.f, 0.f, 0.f};
            float d1[4] = {0.f, 0.f, 0.f, 0.f};
            #pragma unroll
            for (int s = 0; s < 2; s++) {
                uint32_t a0, a1, a2, a3;
                ldm_x4(a0, a1, a2, a3,
                       wp + ((g & 1) * 8 + (lane & 7)) * 80 + s * 32 + (g >> 1) * 16);
                int row = s * 16 + (g & 1) * 8 + (lane & 7);
                int nt  = qn * 2 + (g >> 1);
                uint32_t b0, b1, b2, b3;
                ldm_x4t(b0, b1, b2, b3,
                        xp + row * 128 + ((nt ^ (row & 7)) << 4));
                mma16816(d0, a0, a1, a2, a3, b0, b1);
                mma16816(d1, a0, a1, a2, a3, b2, b3);
            }

            // store D -> WT tile (phase-3 A layout)
            int lr = q * QB + p;
            char* row_ = wt_sh + lr * ROWB;
            int sw = lr & 7;
            #pragma unroll
            for (int i = 0; i < 2; i++) {
                const float* dd = i ? d1 : d0;
                #pragma unroll
                for (int rh = 0; rh < 2; rh++) {
                    int kpt = (lane >> 2) + rh * 8;
                    if (kpt < KPTS) {
                        int c = (qn * 2 + i) * 8 + (lane & 3) * 2;
                        __half2 h = __floats2half2_rn(dd[rh * 2], dd[rh * 2 + 1]);
                        int chunk = (kpt * 8 + (c >> 3)) ^ sw;
                        *(__half2*)(row_ + chunk * 16 + (c & 7) * 2) = h;
                    }
                }
            }
        }

        if (q < NQB - 1) {
            PHASE1_ST((q + 1) & 1)
            STS_X((q + 1) & 1)
        }
        __syncthreads();
    }

    // ---------- Phase 3: HMMA GEMM out[16][64] = wt @ W ----------
    {
        const int kh = wid >> 2;                 // K-half
        const int ng = wid & 3;                  // n-group (2 n-tiles)
        const int rowA = lane & 15;
        const uint32_t a_row = wt_u32 + rowA * ROWB;
        const int swA = rowA & 7;
        const int khalf = lane >> 4;

        float c0[4] = {0.f, 0.f, 0.f, 0.f};
        float c1[4] = {0.f, 0.f, 0.f, 0.f};
        const uint4* Bf = g_Bfrag4 + (ng * NKS + kh * (NKS / 2)) * 32 + lane;

        #pragma unroll 5
        for (int s = 0; s < NKS / 2; s++) {
            int ks = kh * (NKS / 2) + s;
            uint32_t addr = a_row + ((((ks << 1) + khalf) ^ swA) << 4);
            uint32_t a0, a1, a2, a3;
            ldm_x4(a0, a1, a2, a3, addr);
            uint4 b = __ldg(Bf + s * 32);
            mma16816(c0, a0, a1, a2, a3, b.x, b.y);
            mma16816(c1, a0, a1, a2, a3, b.z, b.w);
        }

        // reduce across K-halves via smem (alias over x_sh)
        float4* red4 = (float4*)x_sh;            // 4KB <= 16KB
        __syncthreads();
        if (kh == 1) {
            red4[(ng * 2 + 0) * 32 + lane] = make_float4(c0[0], c0[1], c0[2], c0[3]);
            red4[(ng * 2 + 1) * 32 + lane] = make_float4(c1[0], c1[1], c1[2], c1[3]);
        }
        __syncthreads();
        if (kh == 0) {
            float4 r0 = red4[(ng * 2 + 0) * 32 + lane];
            float4 r1 = red4[(ng * 2 + 1) * 32 + lane];
            c0[0] += r0.x; c0[1] += r0.y; c0[2] += r0.z; c0[3] += r0.w;
            c1[0] += r1.x; c1[1] += r1.y; c1[2] += r1.z; c1[3] += r1.w;
            int ro0 = base + (lane >> 2);
            int ro1 = ro0 + 8;
            int col0 = (ng * 2 + 0) * 8 + (lane & 3) * 2;
            int col1 = (ng * 2 + 1) * 8 + (lane & 3) * 2;
            if (ro0 < N) {
                *(float2*)&out[(long long)ro0 * COUT + col0] = make_float2(c0[0], c0[1]);
                *(float2*)&out[(long long)ro0 * COUT + col1] = make_float2(c1[0], c1[1]);
            }
            if (ro1 < N) {
                *(float2*)&out[(long long)ro1 * COUT + col0] = make_float2(c0[2], c0[3]);
                *(float2*)&out[(long long)ro1 * COUT + col1] = make_float2(c1[2], c1[3]);
            }
        }
    }
}

extern "C" void kernel_launch(void* const* d_in, const int* in_sizes, int n_in,
                              void* d_out, int out_size) {
    const float* q_pts     = (const float*)d_in[0];
    const float* neighbors = (const float*)d_in[2];
    const float* x         = (const float*)d_in[4];
    const float* kp        = (const float*)d_in[5];
    const float* W         = (const float*)d_in[6];
    float* out = (float*)d_out;

    int N = in_sizes[0] / 3;

    cudaFuncSetAttribute(kpconv_kernel,
                         cudaFuncAttributeMaxDynamicSharedMemorySize, SMEM_TOTAL);

    pack_bfrag<<<(4 * NKS * 32 + 255) / 256, 256>>>(W);
    int grid = (N + PBLK - 1) / PBLK;
    kpconv_kernel<<<grid, THREADS, SMEM_TOTAL>>>(q_pts, neighbors, x, kp, out, N);
}